// round 1
// baseline (speedup 1.0000x reference)
#include <cuda_runtime.h>

#define B_  4
#define T_  1024
#define TT  2048
#define D_  512
#define H_  8
#define HD  64

// Scratch (allocation-free rule: __device__ globals)
__device__ float g_Q[B_*H_*TT*HD];   // (b,h,t,hd)
__device__ float g_K[B_*H_*TT*HD];
__device__ float g_V[B_*H_*TT*HD];
__device__ float g_Y[B_*TT*D_];      // attention output, (b,t,d)

// ---------------------------------------------------------------------------
// QKV GEMM: X(4096x512) @ W(512x1536) + bias -> scatter into g_Q/g_K/g_V
// 128x128 block tile, 16 k-tile, 256 threads, 8x8 per thread.
// ---------------------------------------------------------------------------
__global__ __launch_bounds__(256) void qkv_gemm(
    const float* __restrict__ X, const float* __restrict__ W,
    const float* __restrict__ bias, int seq_off)
{
    __shared__ float As[16][132];   // [k][m], padded
    __shared__ float Bs[16][128];   // [k][n]

    const int tid = threadIdx.x;
    const int m0  = blockIdx.y * 128;
    const int n0  = blockIdx.x * 128;
    const int ty  = tid >> 4, tx = tid & 15;

    float acc[8][8];
    #pragma unroll
    for (int i = 0; i < 8; i++)
        #pragma unroll
        for (int j = 0; j < 8; j++) acc[i][j] = 0.f;

    for (int k0 = 0; k0 < 512; k0 += 16) {
        #pragma unroll
        for (int u = 0; u < 2; u++) {
            int f = tid + u * 256;
            int r = f >> 2, c4 = f & 3;
            float4 v = *(const float4*)(X + (size_t)(m0 + r) * 512 + k0 + c4 * 4);
            As[c4*4+0][r] = v.x; As[c4*4+1][r] = v.y;
            As[c4*4+2][r] = v.z; As[c4*4+3][r] = v.w;
        }
        #pragma unroll
        for (int u = 0; u < 2; u++) {
            int f = tid + u * 256;
            int kr = f >> 5, c4 = f & 31;
            *(float4*)(&Bs[kr][c4*4]) =
                *(const float4*)(W + (size_t)(k0 + kr) * 1536 + n0 + c4 * 4);
        }
        __syncthreads();

        #pragma unroll
        for (int kk = 0; kk < 16; kk++) {
            float a[8], b[8];
            *(float4*)(a)     = *(const float4*)(&As[kk][ty*8]);
            *(float4*)(a + 4) = *(const float4*)(&As[kk][ty*8 + 4]);
            *(float4*)(b)     = *(const float4*)(&Bs[kk][tx*8]);
            *(float4*)(b + 4) = *(const float4*)(&Bs[kk][tx*8 + 4]);
            #pragma unroll
            for (int i = 0; i < 8; i++)
                #pragma unroll
                for (int j = 0; j < 8; j++)
                    acc[i][j] = fmaf(a[i], b[j], acc[i][j]);
        }
        __syncthreads();
    }

    #pragma unroll
    for (int i = 0; i < 8; i++) {
        int row = m0 + ty * 8 + i;
        int b   = row >> 10;
        int tg  = (row & 1023) + seq_off;
        #pragma unroll
        for (int j = 0; j < 8; j++) {
            int col = n0 + tx * 8 + j;
            float v = acc[i][j] + bias[col];
            int sel = col >> 9;       // 0=Q 1=K 2=V
            int c   = col & 511;
            int h   = c >> 6, dd = c & 63;
            float* dst = (sel == 0) ? g_Q : ((sel == 1) ? g_K : g_V);
            dst[((((size_t)b * H_ + h) * TT + tg) << 6) + dd] = v;
        }
    }
}

// ---------------------------------------------------------------------------
// Flash attention: one block per (bh, 64-row Q tile). 256 threads.
// 4x4 micro tile per thread for both S and O. Online softmax.
// mask: t_q >= t_k (masked -> -1e30; diagonal guarantees a finite row max).
// ---------------------------------------------------------------------------
__global__ __launch_bounds__(256) void attn_kernel(
    const int* __restrict__ t_self, const int* __restrict__ t_cross)
{
    extern __shared__ float sm[];
    const int LDQ = 68;
    float* Qs = sm;
    float* Ks = Qs + 64 * LDQ;
    float* Vs = Ks + 64 * LDQ;
    float* Ps = Vs + 64 * LDQ;
    int*   tqs = (int*)(Ps + 64 * LDQ);
    int*   tks = tqs + 64;

    const int tid = threadIdx.x;
    const int bh  = blockIdx.y;
    const int b   = bh >> 3;
    const int q0  = blockIdx.x * 64;

    const float* Qbh = g_Q + (size_t)bh * TT * HD;
    const float* Kbh = g_K + (size_t)bh * TT * HD;
    const float* Vbh = g_V + (size_t)bh * TT * HD;

    #pragma unroll
    for (int u = 0; u < 4; u++) {
        int f = tid + u * 256;
        int r = f >> 4, c4 = f & 15;
        *(float4*)(&Qs[r * LDQ + c4 * 4]) =
            *(const float4*)(Qbh + (size_t)(q0 + r) * HD + c4 * 4);
    }
    if (tid < 64) {
        int qg = q0 + tid;
        tqs[tid] = (qg < T_) ? t_self[b * T_ + qg] : t_cross[b * T_ + qg - T_];
    }

    const int ty = tid >> 4, tx = tid & 15;
    const int qr = ty * 4;   // local q rows qr..qr+3
    const int kc = tx * 4;   // local k cols / v cols

    float m_run[4], l_run[4], o[4][4];
    #pragma unroll
    for (int i = 0; i < 4; i++) {
        m_run[i] = -1e30f; l_run[i] = 0.f;
        #pragma unroll
        for (int j = 0; j < 4; j++) o[i][j] = 0.f;
    }

    for (int kt = 0; kt < 32; kt++) {
        __syncthreads();  // prior iteration done with Ks/Vs/Ps
        const int k0 = kt * 64;
        #pragma unroll
        for (int u = 0; u < 4; u++) {
            int f = tid + u * 256;
            int r = f >> 4, c4 = f & 15;
            *(float4*)(&Ks[r * LDQ + c4 * 4]) =
                *(const float4*)(Kbh + (size_t)(k0 + r) * HD + c4 * 4);
            *(float4*)(&Vs[r * LDQ + c4 * 4]) =
                *(const float4*)(Vbh + (size_t)(k0 + r) * HD + c4 * 4);
        }
        if (tid < 64) {
            int kg = k0 + tid;
            tks[tid] = (kg < T_) ? t_self[b * T_ + kg] : t_cross[b * T_ + kg - T_];
        }
        __syncthreads();

        // S = Q K^T (4x4 per thread)
        float s[4][4];
        #pragma unroll
        for (int i = 0; i < 4; i++)
            #pragma unroll
            for (int j = 0; j < 4; j++) s[i][j] = 0.f;

        #pragma unroll
        for (int dd = 0; dd < 64; dd += 4) {
            float4 qv[4], kv[4];
            #pragma unroll
            for (int i = 0; i < 4; i++)
                qv[i] = *(const float4*)(&Qs[(qr + i) * LDQ + dd]);
            #pragma unroll
            for (int j = 0; j < 4; j++)
                kv[j] = *(const float4*)(&Ks[(kc + j) * LDQ + dd]);
            #pragma unroll
            for (int i = 0; i < 4; i++)
                #pragma unroll
                for (int j = 0; j < 4; j++)
                    s[i][j] += qv[i].x * kv[j].x + qv[i].y * kv[j].y +
                               qv[i].z * kv[j].z + qv[i].w * kv[j].w;
        }

        int tqi[4], tkj[4];
        #pragma unroll
        for (int i = 0; i < 4; i++) tqi[i] = tqs[qr + i];
        #pragma unroll
        for (int j = 0; j < 4; j++) tkj[j] = tks[kc + j];

        #pragma unroll
        for (int i = 0; i < 4; i++) {
            float mt = -1e30f;
            #pragma unroll
            for (int j = 0; j < 4; j++) {
                s[i][j] = (tqi[i] >= tkj[j]) ? s[i][j] * 0.125f : -1e30f;
                mt = fmaxf(mt, s[i][j]);
            }
            #pragma unroll
            for (int off = 8; off >= 1; off >>= 1)
                mt = fmaxf(mt, __shfl_xor_sync(0xffffffffu, mt, off));
            float m_new = fmaxf(m_run[i], mt);
            float corr  = __expf(m_run[i] - m_new);
            float rs = 0.f;
            #pragma unroll
            for (int j = 0; j < 4; j++) {
                float p = __expf(s[i][j] - m_new);
                Ps[(qr + i) * LDQ + kc + j] = p;
                rs += p;
            }
            #pragma unroll
            for (int off = 8; off >= 1; off >>= 1)
                rs += __shfl_xor_sync(0xffffffffu, rs, off);
            l_run[i] = l_run[i] * corr + rs;
            m_run[i] = m_new;
            #pragma unroll
            for (int j = 0; j < 4; j++) o[i][j] *= corr;
        }
        __syncwarp();   // P rows are owned by half-warps; make stores visible

        // O += P V (rows qr.., cols kc..)
        #pragma unroll
        for (int kj = 0; kj < 64; kj++) {
            float4 v = *(const float4*)(&Vs[kj * LDQ + kc]);
            #pragma unroll
            for (int i = 0; i < 4; i++) {
                float p = Ps[(qr + i) * LDQ + kj];
                o[i][0] = fmaf(p, v.x, o[i][0]);
                o[i][1] = fmaf(p, v.y, o[i][1]);
                o[i][2] = fmaf(p, v.z, o[i][2]);
                o[i][3] = fmaf(p, v.w, o[i][3]);
            }
        }
    }

    const int h = bh & 7;
    #pragma unroll
    for (int i = 0; i < 4; i++) {
        float inv = 1.f / l_run[i];
        size_t off = ((size_t)b * TT + q0 + qr + i) * D_ + h * HD + kc;
        float4 r = make_float4(o[i][0] * inv, o[i][1] * inv,
                               o[i][2] * inv, o[i][3] * inv);
        *(float4*)(&g_Y[off]) = r;
    }
}

// ---------------------------------------------------------------------------
// Proj GEMM: g_Y(8192x512) @ W_proj(512x512) + b -> d_out with split remap
// ---------------------------------------------------------------------------
__global__ __launch_bounds__(256) void proj_gemm(
    const float* __restrict__ W, const float* __restrict__ bias,
    float* __restrict__ out)
{
    __shared__ float As[16][132];
    __shared__ float Bs[16][128];

    const int tid = threadIdx.x;
    const int m0  = blockIdx.y * 128;   // M = 8192
    const int n0  = blockIdx.x * 128;   // N = 512
    const int ty  = tid >> 4, tx = tid & 15;

    float acc[8][8];
    #pragma unroll
    for (int i = 0; i < 8; i++)
        #pragma unroll
        for (int j = 0; j < 8; j++) acc[i][j] = 0.f;

    for (int k0 = 0; k0 < 512; k0 += 16) {
        #pragma unroll
        for (int u = 0; u < 2; u++) {
            int f = tid + u * 256;
            int r = f >> 2, c4 = f & 3;
            float4 v = *(const float4*)(g_Y + (size_t)(m0 + r) * 512 + k0 + c4 * 4);
            As[c4*4+0][r] = v.x; As[c4*4+1][r] = v.y;
            As[c4*4+2][r] = v.z; As[c4*4+3][r] = v.w;
        }
        #pragma unroll
        for (int u = 0; u < 2; u++) {
            int f = tid + u * 256;
            int kr = f >> 5, c4 = f & 31;
            *(float4*)(&Bs[kr][c4*4]) =
                *(const float4*)(W + (size_t)(k0 + kr) * 512 + n0 + c4 * 4);
        }
        __syncthreads();

        #pragma unroll
        for (int kk = 0; kk < 16; kk++) {
            float a[8], b[8];
            *(float4*)(a)     = *(const float4*)(&As[kk][ty*8]);
            *(float4*)(a + 4) = *(const float4*)(&As[kk][ty*8 + 4]);
            *(float4*)(b)     = *(const float4*)(&Bs[kk][tx*8]);
            *(float4*)(b + 4) = *(const float4*)(&Bs[kk][tx*8 + 4]);
            #pragma unroll
            for (int i = 0; i < 8; i++)
                #pragma unroll
                for (int j = 0; j < 8; j++)
                    acc[i][j] = fmaf(a[i], b[j], acc[i][j]);
        }
        __syncthreads();
    }

    #pragma unroll
    for (int i = 0; i < 8; i++) {
        int row = m0 + ty * 8 + i;
        int b   = row >> 11;
        int tt  = row & 2047;
        size_t base = (tt < T_)
            ? ((size_t)(b * T_ + tt) * D_)
            : ((size_t)B_ * T_ * D_ + (size_t)(b * T_ + (tt - T_)) * D_);
        #pragma unroll
        for (int j = 0; j < 8; j++) {
            int col = n0 + tx * 8 + j;
            out[base + col] = acc[i][j] + bias[col];
        }
    }
}

// ---------------------------------------------------------------------------
extern "C" void kernel_launch(void* const* d_in, const int* in_sizes, int n_in,
                              void* d_out, int out_size)
{
    const float* self_seq  = (const float*)d_in[0];
    const float* cross_seq = (const float*)d_in[1];
    const int*   t_self    = (const int*)d_in[2];
    const int*   t_cross   = (const int*)d_in[3];
    const float* W_self    = (const float*)d_in[4];
    const float* b_self    = (const float*)d_in[5];
    const float* W_cross   = (const float*)d_in[6];
    const float* b_cross   = (const float*)d_in[7];
    const float* W_proj    = (const float*)d_in[8];
    const float* b_proj    = (const float*)d_in[9];
    float* out = (float*)d_out;

    const int attn_smem = (4 * 64 * 68) * 4 + 2 * 64 * 4;   // 70144 bytes
    cudaFuncSetAttribute(attn_kernel,
                         cudaFuncAttributeMaxDynamicSharedMemorySize, attn_smem);

    // QKV for self (time offset 0) and cross (offset 1024)
    qkv_gemm<<<dim3(12, 32), 256>>>(self_seq,  W_self,  b_self,  0);
    qkv_gemm<<<dim3(12, 32), 256>>>(cross_seq, W_cross, b_cross, 1024);

    // Attention over combined (B,H,2048,64)
    attn_kernel<<<dim3(32, 32), 256, attn_smem>>>(t_self, t_cross);

    // Output projection + split write
    proj_gemm<<<dim3(4, 64), 256>>>(W_proj, b_proj, out);
}

// round 3
// speedup vs baseline: 1.8732x; 1.8732x over previous
#include <cuda_runtime.h>
#include <cstdint>

#define B_  4
#define T_  1024
#define TT  2048
#define D_  512
#define H_  8
#define HD  64

// Scratch (allocation-free rule: __device__ globals)
__device__ float g_Q[B_*H_*TT*HD];   // (b,h,t,hd)
__device__ float g_K[B_*H_*TT*HD];
__device__ float g_V[B_*H_*TT*HD];
__device__ float g_Y[B_*TT*D_];      // attention output, (b,t,d)

__device__ __forceinline__ uint32_t f2tf32(float x) {
    uint32_t r;
    asm("cvt.rna.tf32.f32 %0, %1;" : "=r"(r) : "f"(x));
    return r;
}

__device__ __forceinline__ void mma16n8k8(float* c, const uint32_t* a,
                                          uint32_t b0, uint32_t b1) {
    asm volatile(
        "mma.sync.aligned.m16n8k8.row.col.f32.tf32.tf32.f32 "
        "{%0,%1,%2,%3}, {%4,%5,%6,%7}, {%8,%9}, {%0,%1,%2,%3};"
        : "+f"(c[0]), "+f"(c[1]), "+f"(c[2]), "+f"(c[3])
        : "r"(a[0]), "r"(a[1]), "r"(a[2]), "r"(a[3]), "r"(b0), "r"(b1));
}

// ============================================================================
// QKV GEMM (fp32 SIMT, unchanged from round 1)
// ============================================================================
__global__ __launch_bounds__(256) void qkv_gemm(
    const float* __restrict__ X, const float* __restrict__ W,
    const float* __restrict__ bias, int seq_off)
{
    __shared__ float As[16][132];
    __shared__ float Bs[16][128];

    const int tid = threadIdx.x;
    const int m0  = blockIdx.y * 128;
    const int n0  = blockIdx.x * 128;
    const int ty  = tid >> 4, tx = tid & 15;

    float acc[8][8];
    #pragma unroll
    for (int i = 0; i < 8; i++)
        #pragma unroll
        for (int j = 0; j < 8; j++) acc[i][j] = 0.f;

    for (int k0 = 0; k0 < 512; k0 += 16) {
        #pragma unroll
        for (int u = 0; u < 2; u++) {
            int f = tid + u * 256;
            int r = f >> 2, c4 = f & 3;
            float4 v = *(const float4*)(X + (size_t)(m0 + r) * 512 + k0 + c4 * 4);
            As[c4*4+0][r] = v.x; As[c4*4+1][r] = v.y;
            As[c4*4+2][r] = v.z; As[c4*4+3][r] = v.w;
        }
        #pragma unroll
        for (int u = 0; u < 2; u++) {
            int f = tid + u * 256;
            int kr = f >> 5, c4 = f & 31;
            *(float4*)(&Bs[kr][c4*4]) =
                *(const float4*)(W + (size_t)(k0 + kr) * 1536 + n0 + c4 * 4);
        }
        __syncthreads();

        #pragma unroll
        for (int kk = 0; kk < 16; kk++) {
            float a[8], b[8];
            *(float4*)(a)     = *(const float4*)(&As[kk][ty*8]);
            *(float4*)(a + 4) = *(const float4*)(&As[kk][ty*8 + 4]);
            *(float4*)(b)     = *(const float4*)(&Bs[kk][tx*8]);
            *(float4*)(b + 4) = *(const float4*)(&Bs[kk][tx*8 + 4]);
            #pragma unroll
            for (int i = 0; i < 8; i++)
                #pragma unroll
                for (int j = 0; j < 8; j++)
                    acc[i][j] = fmaf(a[i], b[j], acc[i][j]);
        }
        __syncthreads();
    }

    #pragma unroll
    for (int i = 0; i < 8; i++) {
        int row = m0 + ty * 8 + i;
        int b   = row >> 10;
        int tg  = (row & 1023) + seq_off;
        #pragma unroll
        for (int j = 0; j < 8; j++) {
            int col = n0 + tx * 8 + j;
            float v = acc[i][j] + bias[col];
            int sel = col >> 9;
            int c   = col & 511;
            int h   = c >> 6, dd = c & 63;
            float* dst = (sel == 0) ? g_Q : ((sel == 1) ? g_K : g_V);
            dst[((((size_t)b * H_ + h) * TT + tg) << 6) + dd] = v;
        }
    }
}

// ============================================================================
// mma.sync TF32 flash attention (no-max softmax, S/O in registers)
// CTA = (bh, 128 q-rows). 8 warps x 16 q-rows. 16 k-tiles of 128.
// ============================================================================
#define LDK 68
#define LDV 72
#define LDP 132
#define KS_F  0
#define VS_F  (128*LDK)               // 8704
#define PS_F  (VS_F + 128*LDV)        // 17920
#define TKS_F (PS_F + 8*16*LDP)       // 34816
#define ATTN_SMEM ((TKS_F + 128) * 4) // 139776 bytes

__global__ __launch_bounds__(256) void attn_mma(
    const int* __restrict__ t_self, const int* __restrict__ t_cross)
{
    extern __shared__ float sm[];
    float* Ks = sm + KS_F;          // [128][LDK]
    float* Vs = sm + VS_F;          // [128][LDV]
    float* Ps = sm + PS_F;          // [8][16][LDP] per-warp
    int*  tks = (int*)(sm + TKS_F); // [128]

    const int tid  = threadIdx.x;
    const int wid  = tid >> 5;
    const int lane = tid & 31;
    const int g    = lane >> 2;     // 0..7
    const int th   = lane & 3;      // 0..3
    const int bh   = blockIdx.y, b = bh >> 3, h = bh & 7;
    const int q0   = blockIdx.x * 128;

    const float* Qg = g_Q + (size_t)bh * TT * HD;
    const float* Kg = g_K + (size_t)bh * TT * HD;
    const float* Vg = g_V + (size_t)bh * TT * HD;

    const int qr0 = wid * 16 + g;       // local q row (of 128)
    const int qr1 = qr0 + 8;

    // Q A-fragments, resident all kernel: aQ[s][4] for 8 k-steps of 8
    uint32_t aQ[8][4];
    #pragma unroll
    for (int s = 0; s < 8; s++) {
        aQ[s][0] = f2tf32(Qg[(size_t)(q0 + qr0) * HD + s*8 + th]);
        aQ[s][1] = f2tf32(Qg[(size_t)(q0 + qr1) * HD + s*8 + th]);
        aQ[s][2] = f2tf32(Qg[(size_t)(q0 + qr0) * HD + s*8 + th + 4]);
        aQ[s][3] = f2tf32(Qg[(size_t)(q0 + qr1) * HD + s*8 + th + 4]);
    }

    int qg0 = q0 + qr0, qg1 = q0 + qr1;
    const int tq0 = (qg0 < T_) ? t_self[b*T_ + qg0] : t_cross[b*T_ + qg0 - T_];
    const int tq1 = (qg1 < T_) ? t_self[b*T_ + qg1] : t_cross[b*T_ + qg1 - T_];

    float oacc[8][4];
    #pragma unroll
    for (int n = 0; n < 8; n++)
        #pragma unroll
        for (int j = 0; j < 4; j++) oacc[n][j] = 0.f;
    float l0 = 0.f, l1 = 0.f;

    float* Pw = Ps + wid * 16 * LDP;

    #pragma unroll 1
    for (int kt = 0; kt < 16; kt++) {
        const int k0 = kt * 128;
        __syncthreads();   // everyone done reading Ks/Vs from prior iter

        // stage K and V tiles (tf32 bits)
        {
            int r = tid >> 1, cs = (tid & 1) * 32;
            #pragma unroll
            for (int c = 0; c < 32; c += 4) {
                float4 v = *(const float4*)(Kg + (size_t)(k0 + r) * HD + cs + c);
                uint4 t = make_uint4(f2tf32(v.x), f2tf32(v.y), f2tf32(v.z), f2tf32(v.w));
                *(uint4*)(&Ks[r * LDK + cs + c]) = t;
                float4 w = *(const float4*)(Vg + (size_t)(k0 + r) * HD + cs + c);
                uint4 u = make_uint4(f2tf32(w.x), f2tf32(w.y), f2tf32(w.z), f2tf32(w.w));
                *(uint4*)(&Vs[r * LDV + cs + c]) = u;
            }
        }
        if (tid < 128) {
            int kg = k0 + tid;
            tks[tid] = (kg < T_) ? t_self[b*T_ + kg] : t_cross[b*T_ + kg - T_];
        }
        __syncthreads();

        // ---- S = Q K^T : per warp 16x128, 16 nblocks x 8 ksteps ----
        float sacc[16][4];
        #pragma unroll
        for (int n = 0; n < 16; n++)
            #pragma unroll
            for (int j = 0; j < 4; j++) sacc[n][j] = 0.f;

        #pragma unroll
        for (int nb = 0; nb < 16; nb++) {
            const float* krow = &Ks[(nb*8 + g) * LDK];
            #pragma unroll
            for (int s = 0; s < 8; s++) {
                uint32_t b0 = *(const uint32_t*)&krow[s*8 + th];
                uint32_t b1 = *(const uint32_t*)&krow[s*8 + th + 4];
                mma16n8k8(sacc[nb], aQ[s], b0, b1);
            }
        }

        // ---- mask + exp + store P (tf32) to per-warp smem ----
        #pragma unroll
        for (int nb = 0; nb < 16; nb++) {
            int c0 = nb*8 + 2*th, c1 = c0 + 1;
            int tk0 = tks[c0], tk1 = tks[c1];
            float p00 = (tq0 >= tk0) ? __expf(sacc[nb][0] * 0.125f) : 0.f;
            float p01 = (tq0 >= tk1) ? __expf(sacc[nb][1] * 0.125f) : 0.f;
            float p10 = (tq1 >= tk0) ? __expf(sacc[nb][2] * 0.125f) : 0.f;
            float p11 = (tq1 >= tk1) ? __expf(sacc[nb][3] * 0.125f) : 0.f;
            l0 += p00 + p01;
            l1 += p10 + p11;
            uint2 u0 = make_uint2(f2tf32(p00), f2tf32(p01));
            uint2 u1 = make_uint2(f2tf32(p10), f2tf32(p11));
            *(uint2*)&Pw[g * LDP + c0]       = u0;
            *(uint2*)&Pw[(g + 8) * LDP + c0] = u1;
        }
        __syncwarp();

        // ---- O += P V : 16 ksteps x 8 nblocks ----
        #pragma unroll
        for (int s2 = 0; s2 < 16; s2++) {
            uint32_t aP[4];
            aP[0] = *(const uint32_t*)&Pw[g * LDP + s2*8 + th];
            aP[1] = *(const uint32_t*)&Pw[(g + 8) * LDP + s2*8 + th];
            aP[2] = *(const uint32_t*)&Pw[g * LDP + s2*8 + th + 4];
            aP[3] = *(const uint32_t*)&Pw[(g + 8) * LDP + s2*8 + th + 4];
            const float* vr0 = &Vs[(s2*8 + th) * LDV];
            const float* vr1 = &Vs[(s2*8 + th + 4) * LDV];
            #pragma unroll
            for (int nb2 = 0; nb2 < 8; nb2++) {
                uint32_t b0 = *(const uint32_t*)&vr0[nb2*8 + g];
                uint32_t b1 = *(const uint32_t*)&vr1[nb2*8 + g];
                mma16n8k8(oacc[nb2], aP, b0, b1);
            }
        }
        __syncwarp();   // P reads done before next iter's stores
    }

    // reduce l within quads (lanes th=0..3 share a q row)
    l0 += __shfl_xor_sync(0xffffffffu, l0, 1);
    l0 += __shfl_xor_sync(0xffffffffu, l0, 2);
    l1 += __shfl_xor_sync(0xffffffffu, l1, 1);
    l1 += __shfl_xor_sync(0xffffffffu, l1, 2);
    float inv0 = 1.f / l0, inv1 = 1.f / l1;

    float* d0 = g_Y + ((size_t)(b * TT + q0 + qr0)) * D_ + h * HD;
    float* d1 = g_Y + ((size_t)(b * TT + q0 + qr1)) * D_ + h * HD;
    #pragma unroll
    for (int nb2 = 0; nb2 < 8; nb2++) {
        int c = nb2*8 + 2*th;
        *(float2*)&d0[c] = make_float2(oacc[nb2][0] * inv0, oacc[nb2][1] * inv0);
        *(float2*)&d1[c] = make_float2(oacc[nb2][2] * inv1, oacc[nb2][3] * inv1);
    }
}

// ============================================================================
// Proj GEMM (fp32 SIMT, unchanged)
// ============================================================================
__global__ __launch_bounds__(256) void proj_gemm(
    const float* __restrict__ W, const float* __restrict__ bias,
    float* __restrict__ out)
{
    __shared__ float As[16][132];
    __shared__ float Bs[16][128];

    const int tid = threadIdx.x;
    const int m0  = blockIdx.y * 128;
    const int n0  = blockIdx.x * 128;
    const int ty  = tid >> 4, tx = tid & 15;

    float acc[8][8];
    #pragma unroll
    for (int i = 0; i < 8; i++)
        #pragma unroll
        for (int j = 0; j < 8; j++) acc[i][j] = 0.f;

    for (int k0 = 0; k0 < 512; k0 += 16) {
        #pragma unroll
        for (int u = 0; u < 2; u++) {
            int f = tid + u * 256;
            int r = f >> 2, c4 = f & 3;
            float4 v = *(const float4*)(g_Y + (size_t)(m0 + r) * 512 + k0 + c4 * 4);
            As[c4*4+0][r] = v.x; As[c4*4+1][r] = v.y;
            As[c4*4+2][r] = v.z; As[c4*4+3][r] = v.w;
        }
        #pragma unroll
        for (int u = 0; u < 2; u++) {
            int f = tid + u * 256;
            int kr = f >> 5, c4 = f & 31;
            *(float4*)(&Bs[kr][c4*4]) =
                *(const float4*)(W + (size_t)(k0 + kr) * 512 + n0 + c4 * 4);
        }
        __syncthreads();

        #pragma unroll
        for (int kk = 0; kk < 16; kk++) {
            float a[8], b[8];
            *(float4*)(a)     = *(const float4*)(&As[kk][ty*8]);
            *(float4*)(a + 4) = *(const float4*)(&As[kk][ty*8 + 4]);
            *(float4*)(b)     = *(const float4*)(&Bs[kk][tx*8]);
            *(float4*)(b + 4) = *(const float4*)(&Bs[kk][tx*8 + 4]);
            #pragma unroll
            for (int i = 0; i < 8; i++)
                #pragma unroll
                for (int j = 0; j < 8; j++)
                    acc[i][j] = fmaf(a[i], b[j], acc[i][j]);
        }
        __syncthreads();
    }

    #pragma unroll
    for (int i = 0; i < 8; i++) {
        int row = m0 + ty * 8 + i;
        int b   = row >> 11;
        int tt  = row & 2047;
        size_t base = (tt < T_)
            ? ((size_t)(b * T_ + tt) * D_)
            : ((size_t)B_ * T_ * D_ + (size_t)(b * T_ + (tt - T_)) * D_);
        #pragma unroll
        for (int j = 0; j < 8; j++) {
            int col = n0 + tx * 8 + j;
            out[base + col] = acc[i][j] + bias[col];
        }
    }
}

// ---------------------------------------------------------------------------
extern "C" void kernel_launch(void* const* d_in, const int* in_sizes, int n_in,
                              void* d_out, int out_size)
{
    const float* self_seq  = (const float*)d_in[0];
    const float* cross_seq = (const float*)d_in[1];
    const int*   t_self    = (const int*)d_in[2];
    const int*   t_cross   = (const int*)d_in[3];
    const float* W_self    = (const float*)d_in[4];
    const float* b_self    = (const float*)d_in[5];
    const float* W_cross   = (const float*)d_in[6];
    const float* b_cross   = (const float*)d_in[7];
    const float* W_proj    = (const float*)d_in[8];
    const float* b_proj    = (const float*)d_in[9];
    float* out = (float*)d_out;

    cudaFuncSetAttribute(attn_mma,
                         cudaFuncAttributeMaxDynamicSharedMemorySize, ATTN_SMEM);

    qkv_gemm<<<dim3(12, 32), 256>>>(self_seq,  W_self,  b_self,  0);
    qkv_gemm<<<dim3(12, 32), 256>>>(cross_seq, W_cross, b_cross, 1024);

    attn_mma<<<dim3(16, 32), 256, ATTN_SMEM>>>(t_self, t_cross);

    proj_gemm<<<dim3(4, 64), 256>>>(W_proj, b_proj, out);
}

// round 4
// speedup vs baseline: 3.7322x; 1.9924x over previous
#include <cuda_runtime.h>
#include <cstdint>

#define B_  4
#define T_  1024
#define TT  2048
#define D_  512
#define H_  8
#define HD  64

// Scratch (allocation-free rule: __device__ globals).
// g_Q/g_K/g_V hold tf32-rounded bits (stored as float).
__device__ float g_Q[B_*H_*TT*HD];   // (b,h,t,hd)
__device__ float g_K[B_*H_*TT*HD];
__device__ float g_V[B_*H_*TT*HD];
__device__ float g_Y[B_*TT*D_];      // attention output fp32, (b,t,d)

__device__ __forceinline__ uint32_t f2tf32(float x) {
    uint32_t r;
    asm("cvt.rna.tf32.f32 %0, %1;" : "=r"(r) : "f"(x));
    return r;
}

__device__ __forceinline__ void mma16n8k8(float* c, const uint32_t* a,
                                          uint32_t b0, uint32_t b1) {
    asm volatile(
        "mma.sync.aligned.m16n8k8.row.col.f32.tf32.tf32.f32 "
        "{%0,%1,%2,%3}, {%4,%5,%6,%7}, {%8,%9}, {%0,%1,%2,%3};"
        : "+f"(c[0]), "+f"(c[1]), "+f"(c[2]), "+f"(c[3])
        : "r"(a[0]), "r"(a[1]), "r"(a[2]), "r"(a[3]), "r"(b0), "r"(b1));
}

__device__ __forceinline__ void cp16(uint32_t dst, const void* src) {
    asm volatile("cp.async.cg.shared.global [%0], [%1], 16;"
                 :: "r"(dst), "l"(src) : "memory");
}
#define CP_COMMIT() asm volatile("cp.async.commit_group;" ::: "memory")
#define CP_WAIT(n)  asm volatile("cp.async.wait_group %0;" :: "n"(n) : "memory")

__device__ __forceinline__ uint32_t smem_u32(const void* p) {
    uint32_t a;
    asm("{ .reg .u64 t; cvta.to.shared.u64 t, %1; cvt.u32.u64 %0, t; }"
        : "=r"(a) : "l"(p));
    return a;
}

// ============================================================================
// QKV GEMM, tf32 mma.sync: X(4096x512) @ W(512x1536) + bias -> g_Q/g_K/g_V
// CTA 128x128, 8 warps (4m x 2n), warp 32x64. grid.z selects self/cross.
// ============================================================================
#define LDA 36
#define LDB 136

__global__ __launch_bounds__(256, 2) void qkv_mma(
    const float* __restrict__ Xs, const float* __restrict__ Xc,
    const float* __restrict__ Ws, const float* __restrict__ Wc,
    const float* __restrict__ bS, const float* __restrict__ bC)
{
    __shared__ float As[128 * LDA];
    __shared__ float Bs[32 * LDB];

    const int z = blockIdx.z;
    const float* X    = z ? Xc : Xs;
    const float* W    = z ? Wc : Ws;
    const float* bias = z ? bC : bS;
    const int seq_off = z ? 1024 : 0;

    const int tid  = threadIdx.x;
    const int wid  = tid >> 5, lane = tid & 31;
    const int g = lane >> 2, th = lane & 3;
    const int wm = wid & 3, wn = wid >> 2;
    const int m0 = blockIdx.y * 128, n0 = blockIdx.x * 128;

    float acc[2][8][4];
    #pragma unroll
    for (int mt = 0; mt < 2; mt++)
        #pragma unroll
        for (int nt = 0; nt < 8; nt++)
            #pragma unroll
            for (int j = 0; j < 4; j++) acc[mt][nt][j] = 0.f;

    for (int k0 = 0; k0 < 512; k0 += 32) {
        // stage A 128x32 (cvt tf32)
        #pragma unroll
        for (int i = 0; i < 4; i++) {
            int cid = tid + i * 256;
            int r = cid >> 3, kc = cid & 7;
            float4 v = *(const float4*)(X + (size_t)(m0 + r) * 512 + k0 + kc * 4);
            uint4 t = make_uint4(f2tf32(v.x), f2tf32(v.y), f2tf32(v.z), f2tf32(v.w));
            *(uint4*)(&As[r * LDA + kc * 4]) = t;
        }
        // stage B 32x128 (cvt tf32)
        #pragma unroll
        for (int i = 0; i < 4; i++) {
            int cid = tid + i * 256;
            int kr = cid >> 5, nc = cid & 31;
            float4 v = *(const float4*)(W + (size_t)(k0 + kr) * 1536 + n0 + nc * 4);
            uint4 t = make_uint4(f2tf32(v.x), f2tf32(v.y), f2tf32(v.z), f2tf32(v.w));
            *(uint4*)(&Bs[kr * LDB + nc * 4]) = t;
        }
        __syncthreads();

        #pragma unroll
        for (int s = 0; s < 4; s++) {
            uint32_t aF[2][4];
            #pragma unroll
            for (int mt = 0; mt < 2; mt++) {
                int rb = wm * 32 + mt * 16 + g;
                aF[mt][0] = __float_as_uint(As[rb * LDA + s*8 + th]);
                aF[mt][1] = __float_as_uint(As[(rb + 8) * LDA + s*8 + th]);
                aF[mt][2] = __float_as_uint(As[rb * LDA + s*8 + th + 4]);
                aF[mt][3] = __float_as_uint(As[(rb + 8) * LDA + s*8 + th + 4]);
            }
            #pragma unroll
            for (int nt = 0; nt < 8; nt++) {
                int nc = wn * 64 + nt * 8 + g;
                uint32_t b0 = __float_as_uint(Bs[(s*8 + th) * LDB + nc]);
                uint32_t b1 = __float_as_uint(Bs[(s*8 + th + 4) * LDB + nc]);
                mma16n8k8(acc[0][nt], aF[0], b0, b1);
                mma16n8k8(acc[1][nt], aF[1], b0, b1);
            }
        }
        __syncthreads();
    }

    // epilogue: +bias, tf32-round, scatter to Q/K/V
    #pragma unroll
    for (int mt = 0; mt < 2; mt++) {
        #pragma unroll
        for (int r2 = 0; r2 < 2; r2++) {
            int row = m0 + wm * 32 + mt * 16 + g + r2 * 8;
            int bb = row >> 10;
            int tg = (row & 1023) + seq_off;
            #pragma unroll
            for (int nt = 0; nt < 8; nt++) {
                int col = n0 + wn * 64 + nt * 8 + 2 * th;
                float v0 = acc[mt][nt][r2*2+0] + bias[col];
                float v1 = acc[mt][nt][r2*2+1] + bias[col+1];
                int sel = col >> 9, c = col & 511;
                int h = c >> 6, dd = c & 63;
                float* dst = (sel == 0) ? g_Q : ((sel == 1) ? g_K : g_V);
                size_t off = ((((size_t)bb * H_ + h) * TT + tg) << 6) + dd;
                dst[off]     = __uint_as_float(f2tf32(v0));
                dst[off + 1] = __uint_as_float(f2tf32(v1));
            }
        }
    }
}

// ============================================================================
// mma.sync TF32 flash attention, cp.async double-buffered K/V.
// CTA = (bh, 128 q-rows). 8 warps x 16 q-rows. 16 k-tiles of 128.
// Q/K/V in gmem are pre-rounded tf32 bits -> staging is a raw copy.
// ============================================================================
#define LDK 68
#define LDV 72
#define LDP 132
#define KS0 0
#define KS1 (128*LDK)            // 8704
#define VS0 (2*128*LDK)          // 17408
#define VS1 (VS0 + 128*LDV)      // 26624
#define PS_ (VS0 + 2*128*LDV)    // 35840
#define TK0 (PS_ + 8*16*LDP)     // 52736
#define TK1 (TK0 + 128)          // 52864
#define ATTN_SMEM ((TK1 + 128) * 4)   // 211968 bytes

__global__ __launch_bounds__(256) void attn_mma(
    const int* __restrict__ t_self, const int* __restrict__ t_cross)
{
    extern __shared__ float sm[];
    const uint32_t sbU = smem_u32(sm);

    const int tid  = threadIdx.x;
    const int wid  = tid >> 5;
    const int lane = tid & 31;
    const int g    = lane >> 2;
    const int th   = lane & 3;
    const int bh   = blockIdx.y, b = bh >> 3, h = bh & 7;
    const int q0   = blockIdx.x * 128;

    const float* Qg = g_Q + (size_t)bh * TT * HD;
    const float* Kg = g_K + (size_t)bh * TT * HD;
    const float* Vg = g_V + (size_t)bh * TT * HD;

    // issue cp.async loads for k-tile kt into buffer buf
    auto issue = [&](int kt, int buf) {
        const int k0 = kt * 128;
        const float* Kb = Kg + (size_t)k0 * HD;
        const float* Vb = Vg + (size_t)k0 * HD;
        const uint32_t ks = sbU + (buf ? KS1 : KS0) * 4;
        const uint32_t vs = sbU + (buf ? VS1 : VS0) * 4;
        #pragma unroll
        for (int i = 0; i < 8; i++) {
            int idx = tid + i * 256;
            int row = idx >> 4, c = idx & 15;
            cp16(ks + (row * LDK + c * 4) * 4, Kb + row * HD + c * 4);
            cp16(vs + (row * LDV + c * 4) * 4, Vb + row * HD + c * 4);
        }
        if (tid < 32) {
            const int* tb = (k0 < T_) ? (t_self + b * T_ + k0)
                                      : (t_cross + b * T_ + k0 - T_);
            cp16(sbU + (buf ? TK1 : TK0) * 4 + tid * 16, tb + tid * 4);
        }
        CP_COMMIT();
    };

    issue(0, 0);

    const int qr0 = wid * 16 + g;
    const int qr1 = qr0 + 8;

    // Q fragments resident all kernel (pre-rounded tf32 bits)
    uint32_t aQ[8][4];
    #pragma unroll
    for (int s = 0; s < 8; s++) {
        aQ[s][0] = __float_as_uint(Qg[(size_t)(q0 + qr0) * HD + s*8 + th]);
        aQ[s][1] = __float_as_uint(Qg[(size_t)(q0 + qr1) * HD + s*8 + th]);
        aQ[s][2] = __float_as_uint(Qg[(size_t)(q0 + qr0) * HD + s*8 + th + 4]);
        aQ[s][3] = __float_as_uint(Qg[(size_t)(q0 + qr1) * HD + s*8 + th + 4]);
    }
    const int qg0 = q0 + qr0, qg1 = q0 + qr1;
    const int tq0 = (qg0 < T_) ? t_self[b*T_ + qg0] : t_cross[b*T_ + qg0 - T_];
    const int tq1 = (qg1 < T_) ? t_self[b*T_ + qg1] : t_cross[b*T_ + qg1 - T_];

    float oacc[8][4];
    #pragma unroll
    for (int n = 0; n < 8; n++)
        #pragma unroll
        for (int j = 0; j < 4; j++) oacc[n][j] = 0.f;
    float l0 = 0.f, l1 = 0.f;

    float* Pw = sm + PS_ + wid * 16 * LDP;
    const float E = 0.125f * 1.44269504f;   // scale * log2(e)

    #pragma unroll 1
    for (int kt = 0; kt < 16; kt++) {
        const int buf = kt & 1;
        if (kt < 15) { issue(kt + 1, buf ^ 1); CP_WAIT(1); }
        else         { CP_WAIT(0); }
        __syncthreads();

        const float* Ks = sm + (buf ? KS1 : KS0);
        const float* Vs = sm + (buf ? VS1 : VS0);
        const int* tks  = (const int*)(sm + (buf ? TK1 : TK0));

        // ---- S = Q K^T ----
        float sacc[16][4];
        #pragma unroll
        for (int n = 0; n < 16; n++)
            #pragma unroll
            for (int j = 0; j < 4; j++) sacc[n][j] = 0.f;

        #pragma unroll
        for (int nb = 0; nb < 16; nb++) {
            const float* krow = &Ks[(nb*8 + g) * LDK];
            #pragma unroll
            for (int s = 0; s < 8; s++) {
                uint32_t b0 = __float_as_uint(krow[s*8 + th]);
                uint32_t b1 = __float_as_uint(krow[s*8 + th + 4]);
                mma16n8k8(sacc[nb], aQ[s], b0, b1);
            }
        }

        // ---- mask + exp + store P ----
        #pragma unroll
        for (int nb = 0; nb < 16; nb++) {
            int c0 = nb*8 + 2*th, c1 = c0 + 1;
            int tk0 = tks[c0], tk1 = tks[c1];
            float p00 = (tq0 >= tk0) ? exp2f(sacc[nb][0] * E) : 0.f;
            float p01 = (tq0 >= tk1) ? exp2f(sacc[nb][1] * E) : 0.f;
            float p10 = (tq1 >= tk0) ? exp2f(sacc[nb][2] * E) : 0.f;
            float p11 = (tq1 >= tk1) ? exp2f(sacc[nb][3] * E) : 0.f;
            l0 += p00 + p01;
            l1 += p10 + p11;
            *(uint2*)&Pw[g * LDP + c0]       = make_uint2(f2tf32(p00), f2tf32(p01));
            *(uint2*)&Pw[(g + 8) * LDP + c0] = make_uint2(f2tf32(p10), f2tf32(p11));
        }
        __syncwarp();

        // ---- O += P V ----
        #pragma unroll
        for (int s2 = 0; s2 < 16; s2++) {
            uint32_t aP[4];
            aP[0] = __float_as_uint(Pw[g * LDP + s2*8 + th]);
            aP[1] = __float_as_uint(Pw[(g + 8) * LDP + s2*8 + th]);
            aP[2] = __float_as_uint(Pw[g * LDP + s2*8 + th + 4]);
            aP[3] = __float_as_uint(Pw[(g + 8) * LDP + s2*8 + th + 4]);
            const float* vr0 = &Vs[(s2*8 + th) * LDV];
            const float* vr1 = &Vs[(s2*8 + th + 4) * LDV];
            #pragma unroll
            for (int nb2 = 0; nb2 < 8; nb2++) {
                uint32_t b0 = __float_as_uint(vr0[nb2*8 + g]);
                uint32_t b1 = __float_as_uint(vr1[nb2*8 + g]);
                mma16n8k8(oacc[nb2], aP, b0, b1);
            }
        }
        __syncthreads();   // buffer reuse fence (and P private per warp)
    }

    l0 += __shfl_xor_sync(0xffffffffu, l0, 1);
    l0 += __shfl_xor_sync(0xffffffffu, l0, 2);
    l1 += __shfl_xor_sync(0xffffffffu, l1, 1);
    l1 += __shfl_xor_sync(0xffffffffu, l1, 2);
    float inv0 = 1.f / l0, inv1 = 1.f / l1;

    float* d0 = g_Y + ((size_t)(b * TT + q0 + qr0)) * D_ + h * HD;
    float* d1 = g_Y + ((size_t)(b * TT + q0 + qr1)) * D_ + h * HD;
    #pragma unroll
    for (int nb2 = 0; nb2 < 8; nb2++) {
        int c = nb2*8 + 2*th;
        *(float2*)&d0[c] = make_float2(oacc[nb2][0] * inv0, oacc[nb2][1] * inv0);
        *(float2*)&d1[c] = make_float2(oacc[nb2][2] * inv1, oacc[nb2][3] * inv1);
    }
}

// ============================================================================
// Proj GEMM, tf32 mma.sync: g_Y(8192x512) @ W(512x512) + b -> out (split remap)
// ============================================================================
__global__ __launch_bounds__(256, 2) void proj_mma(
    const float* __restrict__ W, const float* __restrict__ bias,
    float* __restrict__ out)
{
    __shared__ float As[128 * LDA];
    __shared__ float Bs[32 * LDB];

    const int tid  = threadIdx.x;
    const int wid  = tid >> 5, lane = tid & 31;
    const int g = lane >> 2, th = lane & 3;
    const int wm = wid & 3, wn = wid >> 2;
    const int m0 = blockIdx.y * 128, n0 = blockIdx.x * 128;

    float acc[2][8][4];
    #pragma unroll
    for (int mt = 0; mt < 2; mt++)
        #pragma unroll
        for (int nt = 0; nt < 8; nt++)
            #pragma unroll
            for (int j = 0; j < 4; j++) acc[mt][nt][j] = 0.f;

    for (int k0 = 0; k0 < 512; k0 += 32) {
        #pragma unroll
        for (int i = 0; i < 4; i++) {
            int cid = tid + i * 256;
            int r = cid >> 3, kc = cid & 7;
            float4 v = *(const float4*)(g_Y + (size_t)(m0 + r) * 512 + k0 + kc * 4);
            uint4 t = make_uint4(f2tf32(v.x), f2tf32(v.y), f2tf32(v.z), f2tf32(v.w));
            *(uint4*)(&As[r * LDA + kc * 4]) = t;
        }
        #pragma unroll
        for (int i = 0; i < 4; i++) {
            int cid = tid + i * 256;
            int kr = cid >> 5, nc = cid & 31;
            float4 v = *(const float4*)(W + (size_t)(k0 + kr) * 512 + n0 + nc * 4);
            uint4 t = make_uint4(f2tf32(v.x), f2tf32(v.y), f2tf32(v.z), f2tf32(v.w));
            *(uint4*)(&Bs[kr * LDB + nc * 4]) = t;
        }
        __syncthreads();

        #pragma unroll
        for (int s = 0; s < 4; s++) {
            uint32_t aF[2][4];
            #pragma unroll
            for (int mt = 0; mt < 2; mt++) {
                int rb = wm * 32 + mt * 16 + g;
                aF[mt][0] = __float_as_uint(As[rb * LDA + s*8 + th]);
                aF[mt][1] = __float_as_uint(As[(rb + 8) * LDA + s*8 + th]);
                aF[mt][2] = __float_as_uint(As[rb * LDA + s*8 + th + 4]);
                aF[mt][3] = __float_as_uint(As[(rb + 8) * LDA + s*8 + th + 4]);
            }
            #pragma unroll
            for (int nt = 0; nt < 8; nt++) {
                int nc = wn * 64 + nt * 8 + g;
                uint32_t b0 = __float_as_uint(Bs[(s*8 + th) * LDB + nc]);
                uint32_t b1 = __float_as_uint(Bs[(s*8 + th + 4) * LDB + nc]);
                mma16n8k8(acc[0][nt], aF[0], b0, b1);
                mma16n8k8(acc[1][nt], aF[1], b0, b1);
            }
        }
        __syncthreads();
    }

    #pragma unroll
    for (int mt = 0; mt < 2; mt++) {
        #pragma unroll
        for (int r2 = 0; r2 < 2; r2++) {
            int row = m0 + wm * 32 + mt * 16 + g + r2 * 8;
            int bb = row >> 11;
            int tt = row & 2047;
            size_t base = (tt < T_)
                ? ((size_t)(bb * T_ + tt) * D_)
                : ((size_t)B_ * T_ * D_ + (size_t)(bb * T_ + (tt - T_)) * D_);
            #pragma unroll
            for (int nt = 0; nt < 8; nt++) {
                int col = n0 + wn * 64 + nt * 8 + 2 * th;
                float2 v = make_float2(acc[mt][nt][r2*2+0] + bias[col],
                                       acc[mt][nt][r2*2+1] + bias[col+1]);
                *(float2*)&out[base + col] = v;
            }
        }
    }
}

// ---------------------------------------------------------------------------
extern "C" void kernel_launch(void* const* d_in, const int* in_sizes, int n_in,
                              void* d_out, int out_size)
{
    const float* self_seq  = (const float*)d_in[0];
    const float* cross_seq = (const float*)d_in[1];
    const int*   t_self    = (const int*)d_in[2];
    const int*   t_cross   = (const int*)d_in[3];
    const float* W_self    = (const float*)d_in[4];
    const float* b_self    = (const float*)d_in[5];
    const float* W_cross   = (const float*)d_in[6];
    const float* b_cross   = (const float*)d_in[7];
    const float* W_proj    = (const float*)d_in[8];
    const float* b_proj    = (const float*)d_in[9];
    float* out = (float*)d_out;

    cudaFuncSetAttribute(attn_mma,
                         cudaFuncAttributeMaxDynamicSharedMemorySize, ATTN_SMEM);

    qkv_mma<<<dim3(12, 32, 2), 256>>>(self_seq, cross_seq,
                                      W_self, W_cross, b_self, b_cross);

    attn_mma<<<dim3(16, 32), 256, ATTN_SMEM>>>(t_self, t_cross);

    proj_mma<<<dim3(4, 64), 256>>>(W_proj, b_proj, out);
}

// round 6
// speedup vs baseline: 4.1892x; 1.1224x over previous
#include <cuda_runtime.h>
#include <cstdint>

#define B_  4
#define T_  1024
#define TT  2048
#define D_  512
#define H_  8
#define HD  64

// Scratch (allocation-free rule: __device__ globals).
// g_Q/g_K tf32-rounded (b,h,t,hd). g_Vt tf32-rounded V transposed (b,h,hd,t).
__device__ float g_Q[B_*H_*TT*HD];
__device__ float g_K[B_*H_*TT*HD];
__device__ float g_Vt[B_*H_*HD*TT];
__device__ float g_Y[B_*TT*D_];      // attention output fp32, (b,t,d)

__device__ __forceinline__ uint32_t f2tf32(float x) {
    uint32_t r;
    asm("cvt.rna.tf32.f32 %0, %1;" : "=r"(r) : "f"(x));
    return r;
}
__device__ __forceinline__ float fexp2(float x) {
    float y;
    asm("ex2.approx.f32 %0, %1;" : "=f"(y) : "f"(x));
    return y;
}

__device__ __forceinline__ void mma16n8k8(float* c, const uint32_t* a,
                                          uint32_t b0, uint32_t b1) {
    asm volatile(
        "mma.sync.aligned.m16n8k8.row.col.f32.tf32.tf32.f32 "
        "{%0,%1,%2,%3}, {%4,%5,%6,%7}, {%8,%9}, {%0,%1,%2,%3};"
        : "+f"(c[0]), "+f"(c[1]), "+f"(c[2]), "+f"(c[3])
        : "r"(a[0]), "r"(a[1]), "r"(a[2]), "r"(a[3]), "r"(b0), "r"(b1));
}

__device__ __forceinline__ void cp16(uint32_t dst, const void* src) {
    asm volatile("cp.async.cg.shared.global [%0], [%1], 16;"
                 :: "r"(dst), "l"(src) : "memory");
}
#define CP_COMMIT() asm volatile("cp.async.commit_group;" ::: "memory")
#define CP_WAIT(n)  asm volatile("cp.async.wait_group %0;" :: "n"(n) : "memory")

__device__ __forceinline__ uint32_t smem_u32(const void* p) {
    uint32_t a;
    asm("{ .reg .u64 t; cvta.to.shared.u64 t, %1; cvt.u32.u64 %0, t; }"
        : "=r"(a) : "l"(p));
    return a;
}

// ============================================================================
// QKV GEMM, tf32 mma.sync. V epilogue writes g_Vt (tf32 bits, transposed).
// ============================================================================
#define LDA 36
#define LDB 136

__global__ __launch_bounds__(256, 2) void qkv_mma(
    const float* __restrict__ Xs, const float* __restrict__ Xc,
    const float* __restrict__ Ws, const float* __restrict__ Wc,
    const float* __restrict__ bS, const float* __restrict__ bC)
{
    __shared__ float As[128 * LDA];
    __shared__ float Bs[32 * LDB];

    const int z = blockIdx.z;
    const float* X    = z ? Xc : Xs;
    const float* W    = z ? Wc : Ws;
    const float* bias = z ? bC : bS;
    const int seq_off = z ? 1024 : 0;

    const int tid  = threadIdx.x;
    const int wid  = tid >> 5, lane = tid & 31;
    const int g = lane >> 2, th = lane & 3;
    const int wm = wid & 3, wn = wid >> 2;
    const int m0 = blockIdx.y * 128, n0 = blockIdx.x * 128;

    float acc[2][8][4];
    #pragma unroll
    for (int mt = 0; mt < 2; mt++)
        #pragma unroll
        for (int nt = 0; nt < 8; nt++)
            #pragma unroll
            for (int j = 0; j < 4; j++) acc[mt][nt][j] = 0.f;

    for (int k0 = 0; k0 < 512; k0 += 32) {
        #pragma unroll
        for (int i = 0; i < 4; i++) {
            int cid = tid + i * 256;
            int r = cid >> 3, kc = cid & 7;
            float4 v = *(const float4*)(X + (size_t)(m0 + r) * 512 + k0 + kc * 4);
            uint4 t = make_uint4(f2tf32(v.x), f2tf32(v.y), f2tf32(v.z), f2tf32(v.w));
            *(uint4*)(&As[r * LDA + kc * 4]) = t;
        }
        #pragma unroll
        for (int i = 0; i < 4; i++) {
            int cid = tid + i * 256;
            int kr = cid >> 5, nc = cid & 31;
            float4 v = *(const float4*)(W + (size_t)(k0 + kr) * 1536 + n0 + nc * 4);
            uint4 t = make_uint4(f2tf32(v.x), f2tf32(v.y), f2tf32(v.z), f2tf32(v.w));
            *(uint4*)(&Bs[kr * LDB + nc * 4]) = t;
        }
        __syncthreads();

        #pragma unroll
        for (int s = 0; s < 4; s++) {
            uint32_t aF[2][4];
            #pragma unroll
            for (int mt = 0; mt < 2; mt++) {
                int rb = wm * 32 + mt * 16 + g;
                aF[mt][0] = __float_as_uint(As[rb * LDA + s*8 + th]);
                aF[mt][1] = __float_as_uint(As[(rb + 8) * LDA + s*8 + th]);
                aF[mt][2] = __float_as_uint(As[rb * LDA + s*8 + th + 4]);
                aF[mt][3] = __float_as_uint(As[(rb + 8) * LDA + s*8 + th + 4]);
            }
            #pragma unroll
            for (int nt = 0; nt < 8; nt++) {
                int nc = wn * 64 + nt * 8 + g;
                uint32_t b0 = __float_as_uint(Bs[(s*8 + th) * LDB + nc]);
                uint32_t b1 = __float_as_uint(Bs[(s*8 + th + 4) * LDB + nc]);
                mma16n8k8(acc[0][nt], aF[0], b0, b1);
                mma16n8k8(acc[1][nt], aF[1], b0, b1);
            }
        }
        __syncthreads();
    }

    #pragma unroll
    for (int mt = 0; mt < 2; mt++) {
        #pragma unroll
        for (int r2 = 0; r2 < 2; r2++) {
            int row = m0 + wm * 32 + mt * 16 + g + r2 * 8;
            int bb = row >> 10;
            int tg = (row & 1023) + seq_off;
            #pragma unroll
            for (int nt = 0; nt < 8; nt++) {
                int col = n0 + wn * 64 + nt * 8 + 2 * th;
                float v0 = acc[mt][nt][r2*2+0] + bias[col];
                float v1 = acc[mt][nt][r2*2+1] + bias[col+1];
                int sel = col >> 9, c = col & 511;
                int h = c >> 6, dd = c & 63;
                if (sel == 2) {
                    float* dv = g_Vt + ((((size_t)bb * H_ + h) * HD + dd) * TT) + tg;
                    dv[0]  = __uint_as_float(f2tf32(v0));
                    dv[TT] = __uint_as_float(f2tf32(v1));
                } else {
                    float* dst = (sel == 0) ? g_Q : g_K;
                    size_t off = ((((size_t)bb * H_ + h) * TT + tg) << 6) + dd;
                    dst[off]     = __uint_as_float(f2tf32(v0));
                    dst[off + 1] = __uint_as_float(f2tf32(v1));
                }
            }
        }
    }
}

// ============================================================================
// Flash attention, all-tf32. 8 warps x 32 q-rows (CTA = 256 q-rows).
// K-tiles of 64, cp.async double-buffered. V^T (hd,t) tf32 from producer.
// ============================================================================
#define KT  64
#define NKT 32
#define LDK 68      // floats per K row (t-major)
#define LDV 68      // floats per V^T row (hd-major)
#define LDP 68      // floats per P row
#define K0B 0
#define K1B 17408
#define V0B 34816
#define V1B 52224
#define PB  69632                 // 8 warps x 32 x LDP floats = 69632 B
#define T0B (PB + 69632)          // 139264
#define T1B (T0B + 256)           // 139520
#define ATTN_SMEM 139776

__global__ __launch_bounds__(256) void attn_mma(
    const int* __restrict__ t_self, const int* __restrict__ t_cross)
{
    extern __shared__ char smc[];
    const uint32_t sbU = smem_u32(smc);

    const int tid  = threadIdx.x;
    const int wid  = tid >> 5;
    const int lane = tid & 31;
    const int g    = lane >> 2;
    const int th   = lane & 3;
    const int bh   = blockIdx.y, b = bh >> 3, h = bh & 7;
    const int q0   = blockIdx.x * 256;

    const float* Qg = g_Q + (size_t)bh * TT * HD;
    const float* Kg = g_K + (size_t)bh * TT * HD;
    const float* Vg = g_Vt + (size_t)bh * HD * TT;

    auto issue = [&](int kt, int bufsel) {
        const int k0 = kt * KT;
        const uint32_t kdst = sbU + (bufsel ? K1B : K0B);
        const uint32_t vdst = sbU + (bufsel ? V1B : V0B);
        #pragma unroll
        for (int i = 0; i < 4; i++) {           // K: 64 rows x 256B
            int idx = tid + i * 256;
            int row = idx >> 4, c = idx & 15;
            cp16(kdst + row * (LDK*4) + c * 16,
                 Kg + (size_t)(k0 + row) * HD + c * 4);
        }
        #pragma unroll
        for (int i = 0; i < 4; i++) {           // V^T: 64 rows x 256B
            int idx = tid + i * 256;
            int row = idx >> 4, c = idx & 15;
            cp16(vdst + row * (LDV*4) + c * 16,
                 Vg + (size_t)row * TT + k0 + c * 4);
        }
        if (tid < 16) {
            const int* tb = (k0 < T_) ? (t_self + b * T_ + k0)
                                      : (t_cross + b * T_ + k0 - T_);
            cp16(sbU + (bufsel ? T1B : T0B) + tid * 16, tb + tid * 4);
        }
        CP_COMMIT();
    };
    issue(0, 0);

    const int wr = q0 + wid * 32;

    // Q fragments resident all kernel (pre-rounded tf32 bits)
    uint32_t aQ[2][8][4];
    #pragma unroll
    for (int mt = 0; mt < 2; mt++) {
        const float* qp0 = Qg + (size_t)(wr + mt*16 + g) * HD;
        const float* qp1 = Qg + (size_t)(wr + mt*16 + g + 8) * HD;
        #pragma unroll
        for (int s = 0; s < 8; s++) {
            aQ[mt][s][0] = __float_as_uint(qp0[s*8 + th]);
            aQ[mt][s][1] = __float_as_uint(qp1[s*8 + th]);
            aQ[mt][s][2] = __float_as_uint(qp0[s*8 + th + 4]);
            aQ[mt][s][3] = __float_as_uint(qp1[s*8 + th + 4]);
        }
    }
    int tq[2][2];
    #pragma unroll
    for (int mt = 0; mt < 2; mt++)
        #pragma unroll
        for (int rr = 0; rr < 2; rr++) {
            int qg = wr + mt*16 + g + rr*8;
            tq[mt][rr] = (qg < T_) ? t_self[b*T_ + qg]
                                   : t_cross[b*T_ + qg - T_];
        }

    float oacc[2][8][4];
    #pragma unroll
    for (int mt = 0; mt < 2; mt++)
        #pragma unroll
        for (int n = 0; n < 8; n++)
            #pragma unroll
            for (int j = 0; j < 4; j++) oacc[mt][n][j] = 0.f;
    float l[4] = {0.f, 0.f, 0.f, 0.f};

    float* Pw = (float*)(smc + PB) + wid * 32 * LDP;
    const float E = 0.125f * 1.44269504f;

    #pragma unroll 1
    for (int kt = 0; kt < NKT; kt++) {
        const int buf = kt & 1;
        if (kt < NKT - 1) { issue(kt + 1, buf ^ 1); CP_WAIT(1); }
        else              { CP_WAIT(0); }
        __syncthreads();

        const float* Ks  = (const float*)(smc + (buf ? K1B : K0B));
        const float* Vs  = (const float*)(smc + (buf ? V1B : V0B));
        const int*   tks = (const int*)(smc + (buf ? T1B : T0B));

        // ---- S = Q K^T, mask/exp, store P (tf32) ----
        #pragma unroll
        for (int nb = 0; nb < 8; nb++) {
            float sa0[4] = {0.f,0.f,0.f,0.f};
            float sa1[4] = {0.f,0.f,0.f,0.f};
            const float* krow = &Ks[(nb*8 + g) * LDK];
            #pragma unroll
            for (int s = 0; s < 8; s++) {
                uint32_t b0 = __float_as_uint(krow[s*8 + th]);
                uint32_t b1 = __float_as_uint(krow[s*8 + th + 4]);
                mma16n8k8(sa0, aQ[0][s], b0, b1);
                mma16n8k8(sa1, aQ[1][s], b0, b1);
            }
            const int c0 = nb*8 + 2*th;
            const int tk0 = tks[c0], tk1 = tks[c0 + 1];

            float p00 = (tq[0][0] >= tk0) ? fexp2(sa0[0] * E) : 0.f;
            float p01 = (tq[0][0] >= tk1) ? fexp2(sa0[1] * E) : 0.f;
            float p10 = (tq[0][1] >= tk0) ? fexp2(sa0[2] * E) : 0.f;
            float p11 = (tq[0][1] >= tk1) ? fexp2(sa0[3] * E) : 0.f;
            l[0] += p00 + p01;  l[1] += p10 + p11;
            *(uint2*)&Pw[g * LDP + c0] =
                make_uint2(f2tf32(p00), f2tf32(p01));
            *(uint2*)&Pw[(g + 8) * LDP + c0] =
                make_uint2(f2tf32(p10), f2tf32(p11));

            float q00 = (tq[1][0] >= tk0) ? fexp2(sa1[0] * E) : 0.f;
            float q01 = (tq[1][0] >= tk1) ? fexp2(sa1[1] * E) : 0.f;
            float q10 = (tq[1][1] >= tk0) ? fexp2(sa1[2] * E) : 0.f;
            float q11 = (tq[1][1] >= tk1) ? fexp2(sa1[3] * E) : 0.f;
            l[2] += q00 + q01;  l[3] += q10 + q11;
            *(uint2*)&Pw[(g + 16) * LDP + c0] =
                make_uint2(f2tf32(q00), f2tf32(q01));
            *(uint2*)&Pw[(g + 24) * LDP + c0] =
                make_uint2(f2tf32(q10), f2tf32(q11));
        }
        __syncwarp();   // P is per-warp private

        // ---- O += P V (tf32 m16n8k8; V^T rows = hd) ----
        #pragma unroll
        for (int s2 = 0; s2 < 8; s2++) {
            uint32_t aP[2][4];
            #pragma unroll
            for (int mt = 0; mt < 2; mt++) {
                aP[mt][0] = __float_as_uint(Pw[(mt*16 + g) * LDP + s2*8 + th]);
                aP[mt][1] = __float_as_uint(Pw[(mt*16 + g + 8) * LDP + s2*8 + th]);
                aP[mt][2] = __float_as_uint(Pw[(mt*16 + g) * LDP + s2*8 + th + 4]);
                aP[mt][3] = __float_as_uint(Pw[(mt*16 + g + 8) * LDP + s2*8 + th + 4]);
            }
            #pragma unroll
            for (int nb2 = 0; nb2 < 8; nb2++) {
                const float* vrow = &Vs[(nb2*8 + g) * LDV];
                uint32_t b0 = __float_as_uint(vrow[s2*8 + th]);
                uint32_t b1 = __float_as_uint(vrow[s2*8 + th + 4]);
                mma16n8k8(oacc[0][nb2], aP[0], b0, b1);
                mma16n8k8(oacc[1][nb2], aP[1], b0, b1);
            }
        }
        __syncthreads();   // all reads of buf done before refill
    }

    #pragma unroll
    for (int i = 0; i < 4; i++) {
        l[i] += __shfl_xor_sync(0xffffffffu, l[i], 1);
        l[i] += __shfl_xor_sync(0xffffffffu, l[i], 2);
    }

    #pragma unroll
    for (int mt = 0; mt < 2; mt++)
        #pragma unroll
        for (int rr = 0; rr < 2; rr++) {
            int row = wr + mt*16 + g + rr*8;
            float inv = 1.f / l[mt*2 + rr];
            float* d = g_Y + ((size_t)(b * TT + row)) * D_ + h * HD;
            #pragma unroll
            for (int nb2 = 0; nb2 < 8; nb2++) {
                int c = nb2*8 + 2*th;
                *(float2*)&d[c] = make_float2(oacc[mt][nb2][rr*2+0] * inv,
                                              oacc[mt][nb2][rr*2+1] * inv);
            }
        }
}

// ============================================================================
// Proj GEMM, tf32 mma.sync (unchanged)
// ============================================================================
__global__ __launch_bounds__(256, 2) void proj_mma(
    const float* __restrict__ W, const float* __restrict__ bias,
    float* __restrict__ out)
{
    __shared__ float As[128 * LDA];
    __shared__ float Bs[32 * LDB];

    const int tid  = threadIdx.x;
    const int wid  = tid >> 5, lane = tid & 31;
    const int g = lane >> 2, th = lane & 3;
    const int wm = wid & 3, wn = wid >> 2;
    const int m0 = blockIdx.y * 128, n0 = blockIdx.x * 128;

    float acc[2][8][4];
    #pragma unroll
    for (int mt = 0; mt < 2; mt++)
        #pragma unroll
        for (int nt = 0; nt < 8; nt++)
            #pragma unroll
            for (int j = 0; j < 4; j++) acc[mt][nt][j] = 0.f;

    for (int k0 = 0; k0 < 512; k0 += 32) {
        #pragma unroll
        for (int i = 0; i < 4; i++) {
            int cid = tid + i * 256;
            int r = cid >> 3, kc = cid & 7;
            float4 v = *(const float4*)(g_Y + (size_t)(m0 + r) * 512 + k0 + kc * 4);
            uint4 t = make_uint4(f2tf32(v.x), f2tf32(v.y), f2tf32(v.z), f2tf32(v.w));
            *(uint4*)(&As[r * LDA + kc * 4]) = t;
        }
        #pragma unroll
        for (int i = 0; i < 4; i++) {
            int cid = tid + i * 256;
            int kr = cid >> 5, nc = cid & 31;
            float4 v = *(const float4*)(W + (size_t)(k0 + kr) * 512 + n0 + nc * 4);
            uint4 t = make_uint4(f2tf32(v.x), f2tf32(v.y), f2tf32(v.z), f2tf32(v.w));
            *(uint4*)(&Bs[kr * LDB + nc * 4]) = t;
        }
        __syncthreads();

        #pragma unroll
        for (int s = 0; s < 4; s++) {
            uint32_t aF[2][4];
            #pragma unroll
            for (int mt = 0; mt < 2; mt++) {
                int rb = wm * 32 + mt * 16 + g;
                aF[mt][0] = __float_as_uint(As[rb * LDA + s*8 + th]);
                aF[mt][1] = __float_as_uint(As[(rb + 8) * LDA + s*8 + th]);
                aF[mt][2] = __float_as_uint(As[rb * LDA + s*8 + th + 4]);
                aF[mt][3] = __float_as_uint(As[(rb + 8) * LDA + s*8 + th + 4]);
            }
            #pragma unroll
            for (int nt = 0; nt < 8; nt++) {
                int nc = wn * 64 + nt * 8 + g;
                uint32_t b0 = __float_as_uint(Bs[(s*8 + th) * LDB + nc]);
                uint32_t b1 = __float_as_uint(Bs[(s*8 + th + 4) * LDB + nc]);
                mma16n8k8(acc[0][nt], aF[0], b0, b1);
                mma16n8k8(acc[1][nt], aF[1], b0, b1);
            }
        }
        __syncthreads();
    }

    #pragma unroll
    for (int mt = 0; mt < 2; mt++) {
        #pragma unroll
        for (int r2 = 0; r2 < 2; r2++) {
            int row = m0 + wm * 32 + mt * 16 + g + r2 * 8;
            int bb = row >> 11;
            int tt = row & 2047;
            size_t base = (tt < T_)
                ? ((size_t)(bb * T_ + tt) * D_)
                : ((size_t)B_ * T_ * D_ + (size_t)(bb * T_ + (tt - T_)) * D_);
            #pragma unroll
            for (int nt = 0; nt < 8; nt++) {
                int col = n0 + wn * 64 + nt * 8 + 2 * th;
                float2 v = make_float2(acc[mt][nt][r2*2+0] + bias[col],
                                       acc[mt][nt][r2*2+1] + bias[col+1]);
                *(float2*)&out[base + col] = v;
            }
        }
    }
}

// ---------------------------------------------------------------------------
extern "C" void kernel_launch(void* const* d_in, const int* in_sizes, int n_in,
                              void* d_out, int out_size)
{
    const float* self_seq  = (const float*)d_in[0];
    const float* cross_seq = (const float*)d_in[1];
    const int*   t_self    = (const int*)d_in[2];
    const int*   t_cross   = (const int*)d_in[3];
    const float* W_self    = (const float*)d_in[4];
    const float* b_self    = (const float*)d_in[5];
    const float* W_cross   = (const float*)d_in[6];
    const float* b_cross   = (const float*)d_in[7];
    const float* W_proj    = (const float*)d_in[8];
    const float* b_proj    = (const float*)d_in[9];
    float* out = (float*)d_out;

    cudaFuncSetAttribute(attn_mma,
                         cudaFuncAttributeMaxDynamicSharedMemorySize, ATTN_SMEM);

    qkv_mma<<<dim3(12, 32, 2), 256>>>(self_seq, cross_seq,
                                      W_self, W_cross, b_self, b_cross);

    attn_mma<<<dim3(8, 32), 256, ATTN_SMEM>>>(t_self, t_cross);

    proj_mma<<<dim3(4, 64), 256>>>(W_proj, b_proj, out);
}

// round 7
// speedup vs baseline: 4.5509x; 1.0863x over previous
#include <cuda_runtime.h>
#include <cstdint>

#define B_  4
#define T_  1024
#define TT  2048
#define D_  512
#define H_  8
#define HD  64

// Scratch (allocation-free rule: __device__ globals).
__device__ float g_Q[B_*H_*TT*HD];     // tf32-rounded (b,h,t,hd)
__device__ float g_K[B_*H_*TT*HD];     // tf32-rounded (b,h,t,hd)
__device__ float g_Vt[B_*H_*HD*TT];    // tf32-rounded V^T (b,h,hd,t)
__device__ float g_Y[B_*TT*D_];        // attention out, tf32-rounded (b,t,d)
// tf32-rounded copies of inputs (pre-pass)
__device__ float g_rXs[B_*T_*D_];
__device__ float g_rXc[B_*T_*D_];
__device__ float g_rWs[D_*3*D_];
__device__ float g_rWc[D_*3*D_];
__device__ float g_rWp[D_*D_];

__device__ __forceinline__ uint32_t f2tf32(float x) {
    uint32_t r;
    asm("cvt.rna.tf32.f32 %0, %1;" : "=r"(r) : "f"(x));
    return r;
}
__device__ __forceinline__ float fexp2(float x) {
    float y;
    asm("ex2.approx.f32 %0, %1;" : "=f"(y) : "f"(x));
    return y;
}
__device__ __forceinline__ void mma16n8k8(float* c, const uint32_t* a,
                                          uint32_t b0, uint32_t b1) {
    asm volatile(
        "mma.sync.aligned.m16n8k8.row.col.f32.tf32.tf32.f32 "
        "{%0,%1,%2,%3}, {%4,%5,%6,%7}, {%8,%9}, {%0,%1,%2,%3};"
        : "+f"(c[0]), "+f"(c[1]), "+f"(c[2]), "+f"(c[3])
        : "r"(a[0]), "r"(a[1]), "r"(a[2]), "r"(a[3]), "r"(b0), "r"(b1));
}
__device__ __forceinline__ void cp16(uint32_t dst, const void* src) {
    asm volatile("cp.async.cg.shared.global [%0], [%1], 16;"
                 :: "r"(dst), "l"(src) : "memory");
}
#define CP_COMMIT() asm volatile("cp.async.commit_group;" ::: "memory")
#define CP_WAIT(n)  asm volatile("cp.async.wait_group %0;" :: "n"(n) : "memory")
__device__ __forceinline__ uint32_t smem_u32(const void* p) {
    uint32_t a;
    asm("{ .reg .u64 t; cvta.to.shared.u64 t, %1; cvt.u32.u64 %0, t; }"
        : "=r"(a) : "l"(p));
    return a;
}

// ============================================================================
// Pre-pass: RNA-round a tensor to tf32 bit pattern (float4 granularity)
// ============================================================================
__global__ __launch_bounds__(256) void round_pass(
    const float* __restrict__ src, float* __restrict__ dst, int n4)
{
    int i = blockIdx.x * blockDim.x + threadIdx.x;
    if (i < n4) {
        float4 v = ((const float4*)src)[i];
        uint4 t = make_uint4(f2tf32(v.x), f2tf32(v.y), f2tf32(v.z), f2tf32(v.w));
        ((uint4*)dst)[i] = t;
    }
}

// ============================================================================
// QKV GEMM, tf32 mma.sync, cp.async double-buffered staging (inputs pre-rounded)
// CTA 128x128, 8 warps (4m x 2n). grid.z selects self/cross.
// ============================================================================
#define LDA 36
#define LDB 136
#define ABYTES (128*LDA*4)          // 18432
#define SLABF  (128*LDA + 32*LDB)   // 8960 floats per buffer
#define GEMM_SMEM (2*SLABF*4)       // 71680 bytes

__global__ __launch_bounds__(256, 2) void qkv_mma(
    const float* __restrict__ bS, const float* __restrict__ bC)
{
    extern __shared__ float smf[];
    const uint32_t sbU = smem_u32(smf);

    const int z = blockIdx.z;
    const float* X    = z ? g_rXc : g_rXs;
    const float* W    = z ? g_rWc : g_rWs;
    const float* bias = z ? bC : bS;
    const int seq_off = z ? 1024 : 0;

    const int tid  = threadIdx.x;
    const int wid  = tid >> 5, lane = tid & 31;
    const int g = lane >> 2, th = lane & 3;
    const int wm = wid & 3, wn = wid >> 2;
    const int m0 = blockIdx.y * 128, n0 = blockIdx.x * 128;

    auto stage = [&](int k0, int buf) {
        const uint32_t adst = sbU + (buf ? (uint32_t)(SLABF*4) : 0u);
        const uint32_t bdst = adst + ABYTES;
        #pragma unroll
        for (int i = 0; i < 4; i++) {
            int cid = tid + i * 256;
            int r = cid >> 3, kc = cid & 7;
            cp16(adst + (r*LDA + kc*4)*4, X + (size_t)(m0 + r)*512 + k0 + kc*4);
        }
        #pragma unroll
        for (int i = 0; i < 4; i++) {
            int cid = tid + i * 256;
            int kr = cid >> 5, nc = cid & 31;
            cp16(bdst + (kr*LDB + nc*4)*4, W + (size_t)(k0 + kr)*1536 + n0 + nc*4);
        }
        CP_COMMIT();
    };

    float acc[2][8][4];
    #pragma unroll
    for (int mt = 0; mt < 2; mt++)
        #pragma unroll
        for (int nt = 0; nt < 8; nt++)
            #pragma unroll
            for (int j = 0; j < 4; j++) acc[mt][nt][j] = 0.f;

    stage(0, 0);
    #pragma unroll 1
    for (int it = 0; it < 16; it++) {
        const int buf = it & 1;
        if (it < 15) { stage((it + 1) * 32, buf ^ 1); CP_WAIT(1); }
        else         { CP_WAIT(0); }
        __syncthreads();

        const float* As = smf + (buf ? SLABF : 0);
        const float* Bs = As + 128*LDA;

        #pragma unroll
        for (int s = 0; s < 4; s++) {
            uint32_t aF[2][4];
            #pragma unroll
            for (int mt = 0; mt < 2; mt++) {
                int rb = wm * 32 + mt * 16 + g;
                aF[mt][0] = __float_as_uint(As[rb * LDA + s*8 + th]);
                aF[mt][1] = __float_as_uint(As[(rb + 8) * LDA + s*8 + th]);
                aF[mt][2] = __float_as_uint(As[rb * LDA + s*8 + th + 4]);
                aF[mt][3] = __float_as_uint(As[(rb + 8) * LDA + s*8 + th + 4]);
            }
            #pragma unroll
            for (int nt = 0; nt < 8; nt++) {
                int nc = wn * 64 + nt * 8 + g;
                uint32_t b0 = __float_as_uint(Bs[(s*8 + th) * LDB + nc]);
                uint32_t b1 = __float_as_uint(Bs[(s*8 + th + 4) * LDB + nc]);
                mma16n8k8(acc[0][nt], aF[0], b0, b1);
                mma16n8k8(acc[1][nt], aF[1], b0, b1);
            }
        }
        __syncthreads();
    }

    #pragma unroll
    for (int mt = 0; mt < 2; mt++) {
        #pragma unroll
        for (int r2 = 0; r2 < 2; r2++) {
            int row = m0 + wm * 32 + mt * 16 + g + r2 * 8;
            int bb = row >> 10;
            int tg = (row & 1023) + seq_off;
            #pragma unroll
            for (int nt = 0; nt < 8; nt++) {
                int col = n0 + wn * 64 + nt * 8 + 2 * th;
                float v0 = acc[mt][nt][r2*2+0] + bias[col];
                float v1 = acc[mt][nt][r2*2+1] + bias[col+1];
                int sel = col >> 9, c = col & 511;
                int h = c >> 6, dd = c & 63;
                if (sel == 2) {
                    float* dv = g_Vt + ((((size_t)bb * H_ + h) * HD + dd) * TT) + tg;
                    dv[0]  = __uint_as_float(f2tf32(v0));
                    dv[TT] = __uint_as_float(f2tf32(v1));
                } else {
                    float* dst = (sel == 0) ? g_Q : g_K;
                    size_t off = ((((size_t)bb * H_ + h) * TT + tg) << 6) + dd;
                    dst[off]     = __uint_as_float(f2tf32(v0));
                    dst[off + 1] = __uint_as_float(f2tf32(v1));
                }
            }
        }
    }
}

// ============================================================================
// Flash attention, all-tf32. 8 warps x 16 q-rows (CTA = 128 q-rows),
// 2 CTAs/SM. K-tiles of 64, cp.async double-buffered.
// ============================================================================
#define KT  64
#define NKT 32
#define LDK 68
#define LDV 68
#define LDP 68
#define K0B 0
#define K1B 17408
#define V0B 34816
#define V1B 52224
#define PB  69632                 // 8 warps x 16 x LDP x 4 = 34816
#define T0B 104448
#define T1B 104704
#define ATTN_SMEM 104960

__global__ __launch_bounds__(256, 2) void attn_mma(
    const int* __restrict__ t_self, const int* __restrict__ t_cross)
{
    extern __shared__ char smc[];
    const uint32_t sbU = smem_u32(smc);

    const int tid  = threadIdx.x;
    const int wid  = tid >> 5;
    const int lane = tid & 31;
    const int g    = lane >> 2;
    const int th   = lane & 3;
    const int bh   = blockIdx.y, b = bh >> 3, h = bh & 7;
    const int q0   = blockIdx.x * 128;

    const float* Qg = g_Q + (size_t)bh * TT * HD;
    const float* Kg = g_K + (size_t)bh * TT * HD;
    const float* Vg = g_Vt + (size_t)bh * HD * TT;

    auto issue = [&](int kt, int bufsel) {
        const int k0 = kt * KT;
        const uint32_t kdst = sbU + (bufsel ? K1B : K0B);
        const uint32_t vdst = sbU + (bufsel ? V1B : V0B);
        #pragma unroll
        for (int i = 0; i < 4; i++) {           // K: 64 t-rows x 256B
            int idx = tid + i * 256;
            int row = idx >> 4, c = idx & 15;
            cp16(kdst + row * (LDK*4) + c * 16,
                 Kg + (size_t)(k0 + row) * HD + c * 4);
        }
        #pragma unroll
        for (int i = 0; i < 4; i++) {           // V^T: 64 hd-rows x 256B
            int idx = tid + i * 256;
            int row = idx >> 4, c = idx & 15;
            cp16(vdst + row * (LDV*4) + c * 16,
                 Vg + (size_t)row * TT + k0 + c * 4);
        }
        if (tid < 16) {
            const int* tb = (k0 < T_) ? (t_self + b * T_ + k0)
                                      : (t_cross + b * T_ + k0 - T_);
            cp16(sbU + (bufsel ? T1B : T0B) + tid * 16, tb + tid * 4);
        }
        CP_COMMIT();
    };
    issue(0, 0);

    const int wr = q0 + wid * 16;

    // Q fragments resident all kernel (pre-rounded tf32 bits): 32 regs
    uint32_t aQ[8][4];
    {
        const float* qp0 = Qg + (size_t)(wr + g) * HD;
        const float* qp1 = Qg + (size_t)(wr + g + 8) * HD;
        #pragma unroll
        for (int s = 0; s < 8; s++) {
            aQ[s][0] = __float_as_uint(qp0[s*8 + th]);
            aQ[s][1] = __float_as_uint(qp1[s*8 + th]);
            aQ[s][2] = __float_as_uint(qp0[s*8 + th + 4]);
            aQ[s][3] = __float_as_uint(qp1[s*8 + th + 4]);
        }
    }
    int tq[2];
    #pragma unroll
    for (int rr = 0; rr < 2; rr++) {
        int qg = wr + g + rr*8;
        tq[rr] = (qg < T_) ? t_self[b*T_ + qg] : t_cross[b*T_ + qg - T_];
    }

    float oacc[8][4];
    #pragma unroll
    for (int n = 0; n < 8; n++)
        #pragma unroll
        for (int j = 0; j < 4; j++) oacc[n][j] = 0.f;
    float l0 = 0.f, l1 = 0.f;

    float* Pw = (float*)(smc + PB) + wid * 16 * LDP;
    const float E = 0.125f * 1.44269504f;

    #pragma unroll 1
    for (int kt = 0; kt < NKT; kt++) {
        const int buf = kt & 1;
        if (kt < NKT - 1) { issue(kt + 1, buf ^ 1); CP_WAIT(1); }
        else              { CP_WAIT(0); }
        __syncthreads();

        const float* Ks  = (const float*)(smc + (buf ? K1B : K0B));
        const float* Vs  = (const float*)(smc + (buf ? V1B : V0B));
        const int*   tks = (const int*)(smc + (buf ? T1B : T0B));

        // ---- S = Q K^T, mask/exp, store P (tf32) ----
        #pragma unroll
        for (int nb = 0; nb < 8; nb++) {
            float sa[4] = {0.f, 0.f, 0.f, 0.f};
            const float* krow = &Ks[(nb*8 + g) * LDK];
            #pragma unroll
            for (int s = 0; s < 8; s++) {
                uint32_t b0 = __float_as_uint(krow[s*8 + th]);
                uint32_t b1 = __float_as_uint(krow[s*8 + th + 4]);
                mma16n8k8(sa, aQ[s], b0, b1);
            }
            const int c0 = nb*8 + 2*th;
            const int tk0 = tks[c0], tk1 = tks[c0 + 1];

            float p00 = (tq[0] >= tk0) ? fexp2(sa[0] * E) : 0.f;
            float p01 = (tq[0] >= tk1) ? fexp2(sa[1] * E) : 0.f;
            float p10 = (tq[1] >= tk0) ? fexp2(sa[2] * E) : 0.f;
            float p11 = (tq[1] >= tk1) ? fexp2(sa[3] * E) : 0.f;
            l0 += p00 + p01;  l1 += p10 + p11;
            *(uint2*)&Pw[g * LDP + c0]       = make_uint2(f2tf32(p00), f2tf32(p01));
            *(uint2*)&Pw[(g + 8) * LDP + c0] = make_uint2(f2tf32(p10), f2tf32(p11));
        }
        __syncwarp();   // P is per-warp private

        // ---- O += P V (tf32 m16n8k8; V^T rows = hd) ----
        #pragma unroll
        for (int s2 = 0; s2 < 8; s2++) {
            uint32_t aP[4];
            aP[0] = __float_as_uint(Pw[g * LDP + s2*8 + th]);
            aP[1] = __float_as_uint(Pw[(g + 8) * LDP + s2*8 + th]);
            aP[2] = __float_as_uint(Pw[g * LDP + s2*8 + th + 4]);
            aP[3] = __float_as_uint(Pw[(g + 8) * LDP + s2*8 + th + 4]);
            #pragma unroll
            for (int nb2 = 0; nb2 < 8; nb2++) {
                const float* vrow = &Vs[(nb2*8 + g) * LDV];
                uint32_t b0 = __float_as_uint(vrow[s2*8 + th]);
                uint32_t b1 = __float_as_uint(vrow[s2*8 + th + 4]);
                mma16n8k8(oacc[nb2], aP, b0, b1);
            }
        }
        __syncthreads();   // all reads of buf done before refill
    }

    l0 += __shfl_xor_sync(0xffffffffu, l0, 1);
    l0 += __shfl_xor_sync(0xffffffffu, l0, 2);
    l1 += __shfl_xor_sync(0xffffffffu, l1, 1);
    l1 += __shfl_xor_sync(0xffffffffu, l1, 2);
    float inv[2] = {1.f / l0, 1.f / l1};

    // write g_Y pre-rounded to tf32 (moves proj's A-conversion here; identical)
    #pragma unroll
    for (int rr = 0; rr < 2; rr++) {
        int row = wr + g + rr*8;
        float* d = g_Y + ((size_t)(b * TT + row)) * D_ + h * HD;
        #pragma unroll
        for (int nb2 = 0; nb2 < 8; nb2++) {
            int c = nb2*8 + 2*th;
            *(uint2*)&d[c] = make_uint2(f2tf32(oacc[nb2][rr*2+0] * inv[rr]),
                                        f2tf32(oacc[nb2][rr*2+1] * inv[rr]));
        }
    }
}

// ============================================================================
// Proj GEMM, tf32 mma.sync, cp.async double-buffered (inputs pre-rounded)
// ============================================================================
__global__ __launch_bounds__(256, 2) void proj_mma(
    const float* __restrict__ bias, float* __restrict__ out)
{
    extern __shared__ float smf[];
    const uint32_t sbU = smem_u32(smf);

    const int tid  = threadIdx.x;
    const int wid  = tid >> 5, lane = tid & 31;
    const int g = lane >> 2, th = lane & 3;
    const int wm = wid & 3, wn = wid >> 2;
    const int m0 = blockIdx.y * 128, n0 = blockIdx.x * 128;

    auto stage = [&](int k0, int buf) {
        const uint32_t adst = sbU + (buf ? (uint32_t)(SLABF*4) : 0u);
        const uint32_t bdst = adst + ABYTES;
        #pragma unroll
        for (int i = 0; i < 4; i++) {
            int cid = tid + i * 256;
            int r = cid >> 3, kc = cid & 7;
            cp16(adst + (r*LDA + kc*4)*4, g_Y + (size_t)(m0 + r)*512 + k0 + kc*4);
        }
        #pragma unroll
        for (int i = 0; i < 4; i++) {
            int cid = tid + i * 256;
            int kr = cid >> 5, nc = cid & 31;
            cp16(bdst + (kr*LDB + nc*4)*4, g_rWp + (size_t)(k0 + kr)*512 + n0 + nc*4);
        }
        CP_COMMIT();
    };

    float acc[2][8][4];
    #pragma unroll
    for (int mt = 0; mt < 2; mt++)
        #pragma unroll
        for (int nt = 0; nt < 8; nt++)
            #pragma unroll
            for (int j = 0; j < 4; j++) acc[mt][nt][j] = 0.f;

    stage(0, 0);
    #pragma unroll 1
    for (int it = 0; it < 16; it++) {
        const int buf = it & 1;
        if (it < 15) { stage((it + 1) * 32, buf ^ 1); CP_WAIT(1); }
        else         { CP_WAIT(0); }
        __syncthreads();

        const float* As = smf + (buf ? SLABF : 0);
        const float* Bs = As + 128*LDA;

        #pragma unroll
        for (int s = 0; s < 4; s++) {
            uint32_t aF[2][4];
            #pragma unroll
            for (int mt = 0; mt < 2; mt++) {
                int rb = wm * 32 + mt * 16 + g;
                aF[mt][0] = __float_as_uint(As[rb * LDA + s*8 + th]);
                aF[mt][1] = __float_as_uint(As[(rb + 8) * LDA + s*8 + th]);
                aF[mt][2] = __float_as_uint(As[rb * LDA + s*8 + th + 4]);
                aF[mt][3] = __float_as_uint(As[(rb + 8) * LDA + s*8 + th + 4]);
            }
            #pragma unroll
            for (int nt = 0; nt < 8; nt++) {
                int nc = wn * 64 + nt * 8 + g;
                uint32_t b0 = __float_as_uint(Bs[(s*8 + th) * LDB + nc]);
                uint32_t b1 = __float_as_uint(Bs[(s*8 + th + 4) * LDB + nc]);
                mma16n8k8(acc[0][nt], aF[0], b0, b1);
                mma16n8k8(acc[1][nt], aF[1], b0, b1);
            }
        }
        __syncthreads();
    }

    #pragma unroll
    for (int mt = 0; mt < 2; mt++) {
        #pragma unroll
        for (int r2 = 0; r2 < 2; r2++) {
            int row = m0 + wm * 32 + mt * 16 + g + r2 * 8;
            int bb = row >> 11;
            int tt = row & 2047;
            size_t base = (tt < T_)
                ? ((size_t)(bb * T_ + tt) * D_)
                : ((size_t)B_ * T_ * D_ + (size_t)(bb * T_ + (tt - T_)) * D_);
            #pragma unroll
            for (int nt = 0; nt < 8; nt++) {
                int col = n0 + wn * 64 + nt * 8 + 2 * th;
                float2 v = make_float2(acc[mt][nt][r2*2+0] + bias[col],
                                       acc[mt][nt][r2*2+1] + bias[col+1]);
                *(float2*)&out[base + col] = v;
            }
        }
    }
}

// ---------------------------------------------------------------------------
extern "C" void kernel_launch(void* const* d_in, const int* in_sizes, int n_in,
                              void* d_out, int out_size)
{
    const float* self_seq  = (const float*)d_in[0];
    const float* cross_seq = (const float*)d_in[1];
    const int*   t_self    = (const int*)d_in[2];
    const int*   t_cross   = (const int*)d_in[3];
    const float* W_self    = (const float*)d_in[4];
    const float* b_self    = (const float*)d_in[5];
    const float* W_cross   = (const float*)d_in[6];
    const float* b_cross   = (const float*)d_in[7];
    const float* W_proj    = (const float*)d_in[8];
    const float* b_proj    = (const float*)d_in[9];
    float* out = (float*)d_out;

    cudaFuncSetAttribute(attn_mma,
                         cudaFuncAttributeMaxDynamicSharedMemorySize, ATTN_SMEM);
    cudaFuncSetAttribute(qkv_mma,
                         cudaFuncAttributeMaxDynamicSharedMemorySize, GEMM_SMEM);
    cudaFuncSetAttribute(proj_mma,
                         cudaFuncAttributeMaxDynamicSharedMemorySize, GEMM_SMEM);

    float *rXs, *rXc, *rWs, *rWc, *rWp;
    cudaGetSymbolAddress((void**)&rXs, g_rXs);
    cudaGetSymbolAddress((void**)&rXc, g_rXc);
    cudaGetSymbolAddress((void**)&rWs, g_rWs);
    cudaGetSymbolAddress((void**)&rWc, g_rWc);
    cudaGetSymbolAddress((void**)&rWp, g_rWp);

    // Pre-pass: RNA-round inputs to tf32 (same rounding previously done in
    // the GEMM staging loops — numerics identical, staging becomes cp.async)
    round_pass<<<(B_*T_*D_/4 + 255)/256, 256>>>(self_seq,  rXs, B_*T_*D_/4);
    round_pass<<<(B_*T_*D_/4 + 255)/256, 256>>>(cross_seq, rXc, B_*T_*D_/4);
    round_pass<<<(D_*3*D_/4 + 255)/256, 256>>>(W_self,  rWs, D_*3*D_/4);
    round_pass<<<(D_*3*D_/4 + 255)/256, 256>>>(W_cross, rWc, D_*3*D_/4);
    round_pass<<<(D_*D_/4   + 255)/256, 256>>>(W_proj,  rWp, D_*D_/4);

    qkv_mma<<<dim3(12, 32, 2), 256, GEMM_SMEM>>>(b_self, b_cross);

    attn_mma<<<dim3(16, 32), 256, ATTN_SMEM>>>(t_self, t_cross);

    proj_mma<<<dim3(4, 64), 256, GEMM_SMEM>>>(b_proj, out);
}